// round 8
// baseline (speedup 1.0000x reference)
#include <cuda_runtime.h>
#include <cstdint>

#define BB 4
#define NN 256
#define CC 512
#define HH 8
#define DD 64

// Scratch (allocation-free rule: device globals)
__device__ float g_Q[BB*NN*CC];
__device__ float g_K[BB*NN*CC];
__device__ float g_V[BB*NN*CC];
__device__ float g_S[BB*HH*NN*NN];   // [b][h][i][j] clamped score sums

__device__ __forceinline__ unsigned f2tf(float x){
    unsigned r; asm("cvt.rna.tf32.f32 %0, %1;" : "=r"(r) : "f"(x)); return r;
}

__device__ __forceinline__ void mma8(float* c, const unsigned* a, const unsigned* b){
    asm volatile("mma.sync.aligned.m16n8k8.row.col.f32.tf32.tf32.f32 "
        "{%0,%1,%2,%3}, {%4,%5,%6,%7}, {%8,%9}, {%0,%1,%2,%3};\n"
        : "+f"(c[0]), "+f"(c[1]), "+f"(c[2]), "+f"(c[3])
        : "r"(a[0]), "r"(a[1]), "r"(a[2]), "r"(a[3]), "r"(b[0]), "r"(b[1]));
}

// ---------------------------------------------------------------------------
// Main GEMM + fused attention epilogue (legacy mma.sync tf32 — tcgen05 is
// rejected by this harness's compute_103 PTX target).
// Block 128x256, 8 warps as 2x4 grid of 64x64 warp tiles:
//   smem traffic = 128 B/MMA (vs 192 in the 64x32 R3 design) -> parity with
//   tensor pipe instead of 1.5x oversubscription (R3 was smem-wavefront-bound:
//   l1tex 65.5% vs tensor 37.9% = the 1536:1024 wavefront:MMA ratio).
// Double-buffered smem stages, one barrier per ktile, A-tile reg-staged LDG.
// Swizzle: col' = col ^ (4*(k>>2)); LDK=136 (A), LDB=264 (B); both = 8 mod 32;
// stores and fragment loads verified conflict-free.
// Epilogue: 64-col warp tile == one head -> row-sum via 2 shfls, direct g_S
// store, no atomics. val = D * Q[b,i,c] * K[b,j,c] / 8 -> e_out.
// ---------------------------------------------------------------------------
__global__ void __launch_bounds__(256, 1)
mm_big(const float* __restrict__ A, const float* __restrict__ W,
       float* __restrict__ C)
{
    extern __shared__ unsigned sm[];
    // stage layout (words): As 32*136=4352, Bs 32*264=8448 -> 12800/stage
    unsigned* As[2] = { sm,        sm + 12800 };
    unsigned* Bs[2] = { sm + 4352, sm + 12800 + 4352 };

    const int tid  = threadIdx.x;
    const int lane = tid & 31;
    const int wid  = tid >> 5;
    const int wm = wid >> 2, wn = wid & 3;     // 2 x 4 warp grid, 64x64 tiles
    const int lr = lane >> 2, lc = lane & 3;
    const size_t m0 = (size_t)blockIdx.y * 128;
    const int n0 = blockIdx.x * 256;

    float acc[4][8][4];
    #pragma unroll
    for (int a=0;a<4;a++)
        #pragma unroll
        for (int b=0;b<8;b++)
            #pragma unroll
            for (int c=0;c<4;c++) acc[a][b][c]=0.f;

    float4 a_st[4];

    // ---- A LDG into regs (128x32 tile, 4 float4/thread) ----
    auto ldgA = [&](int kb){
        #pragma unroll
        for (int l = 0; l < 4; l++){
            int idx = l*256 + tid;
            int row = idx >> 3, kq = idx & 7;
            a_st[l] = *(const float4*)(A + (m0 + row)*512 + kb*32 + kq*4);
        }
    };
    // ---- A STS from regs (scattered STS.32, conflict-free) ----
    auto stsA = [&](int st){
        #pragma unroll
        for (int l = 0; l < 4; l++){
            int idx = l*256 + tid;
            int row = idx >> 3, kq = idx & 7;
            int sw = row ^ (4*kq);
            float v[4] = {a_st[l].x, a_st[l].y, a_st[l].z, a_st[l].w};
            #pragma unroll
            for (int c = 0; c < 4; c++)
                As[st][(kq*4+c)*136 + sw] = f2tf(v[c]);
        }
    };
    // ---- B: LDG + cvt + STS.128 (32x256 tile, 8 float4/thread) ----
    auto loadB = [&](int st, int kb){
        #pragma unroll
        for (int l = 0; l < 8; l++){
            int idx = l*256 + tid;
            int k = idx >> 6, cq = idx & 63;
            float4 v = *(const float4*)(W + (size_t)(kb*32+k)*512 + n0 + cq*4);
            int colb = (cq*4) ^ (4*(k>>2));
            uint4 h;
            h.x = f2tf(v.x); h.y = f2tf(v.y); h.z = f2tf(v.z); h.w = f2tf(v.w);
            *(uint4*)&Bs[st][k*264 + colb] = h;
        }
    };

    // prologue: stage 0
    ldgA(0);
    stsA(0);
    loadB(0, 0);
    __syncthreads();

    for (int kb = 0; kb < 16; kb++){
        const int cur = kb & 1;
        if (kb < 15) ldgA(kb + 1);          // global latency hides under MMAs

        #pragma unroll
        for (int k8 = 0; k8 < 4; k8++){
            const int kk = k8*8 + lc;
            const int g0 = 8*k8;            // 4*(kk>>2), warp-constant (lc<4)
            const int g1 = 8*k8 + 4;        // 4*((kk+4)>>2)
            unsigned af[4][4], bf[8][2];
            #pragma unroll
            for (int mt=0; mt<4; mt++){
                int r = wm*64 + mt*16 + lr;
                af[mt][0] = As[cur][kk*136     + (r       ^ g0)];
                af[mt][1] = As[cur][kk*136     + ((r + 8) ^ g0)];
                af[mt][2] = As[cur][(kk+4)*136 + (r       ^ g1)];
                af[mt][3] = As[cur][(kk+4)*136 + ((r + 8) ^ g1)];
            }
            #pragma unroll
            for (int nt=0; nt<8; nt++){
                int c = wn*64 + nt*8 + lr;
                bf[nt][0] = Bs[cur][kk*264     + (c ^ g0)];
                bf[nt][1] = Bs[cur][(kk+4)*264 + (c ^ g1)];
            }
            #pragma unroll
            for (int mt=0; mt<4; mt++)
                #pragma unroll
                for (int nt=0; nt<8; nt++)
                    mma8(acc[mt][nt], af[mt], bf[nt]);
        }

        if (kb < 15){
            const int nxt = cur ^ 1;
            loadB(nxt, kb + 1);
            stsA(nxt);
        }
        __syncthreads();
    }

    // ---------------- fused epilogue ----------------
    const int bidx = (int)(m0 >> 16);
    const int ii   = (int)((m0 >> 8) & 255);
    const int j0   = (int)(m0 & 255);

    float* Qs = (float*)sm;              // reuse stage0 (all reads done)
    if (tid < 256) Qs[tid] = g_Q[((size_t)(bidx*256 + ii))*512 + n0 + tid];
    __syncthreads();

    const int hh = (n0 >> 6) + wn;       // warp's 64 cols = exactly one head
    float qv[8][2];
    #pragma unroll
    for (int nt=0; nt<8; nt++){
        int c = wn*64 + nt*8 + lc*2;
        qv[nt][0] = Qs[c]   * 0.125f;
        qv[nt][1] = Qs[c+1] * 0.125f;
    }

    #pragma unroll
    for (int mt=0; mt<4; mt++){
        int rlA = wm*64 + mt*16 + lr;
        int rlB = rlA + 8;
        const float* KrA = g_K + ((size_t)bidx*256 + j0 + rlA)*512 + n0;
        const float* KrB = g_K + ((size_t)bidx*256 + j0 + rlB)*512 + n0;
        float pA = 0.f, pB = 0.f;
        #pragma unroll
        for (int nt=0; nt<8; nt++){
            int c = wn*64 + nt*8 + lc*2;
            float v0 = acc[mt][nt][0] * qv[nt][0] * KrA[c];
            float v1 = acc[mt][nt][1] * qv[nt][1] * KrA[c+1];
            float v2 = acc[mt][nt][2] * qv[nt][0] * KrB[c];
            float v3 = acc[mt][nt][3] * qv[nt][1] * KrB[c+1];
            *(float2*)(C + (m0 + rlA)*512 + n0 + c) = make_float2(v0, v1);
            *(float2*)(C + (m0 + rlB)*512 + n0 + c) = make_float2(v2, v3);
            pA += v0 + v1;
            pB += v2 + v3;
        }
        // sum over lc group (4 lanes) -> full 64-col head sum
        pA += __shfl_xor_sync(0xffffffffu, pA, 1);
        pA += __shfl_xor_sync(0xffffffffu, pA, 2);
        pB += __shfl_xor_sync(0xffffffffu, pB, 1);
        pB += __shfl_xor_sync(0xffffffffu, pB, 2);
        if (lc == 0){
            float sA = fminf(fmaxf(pA, -5.f), 5.f);
            float sB = fminf(fmaxf(pB, -5.f), 5.f);
            g_S[(((size_t)(bidx*8 + hh))*256 + ii)*256 + j0 + rlA] = sA;
            g_S[(((size_t)(bidx*8 + hh))*256 + ii)*256 + j0 + rlB] = sB;
        }
    }
}

// ---------------------------------------------------------------------------
// QKV projections: one launch, blockIdx.z selects {Wq,Wk,Wv} -> {g_Q,g_K,g_V}.
// 3x tf32 split, swizzled smem (R3 layout, verified conflict-free).
// ---------------------------------------------------------------------------
__global__ void __launch_bounds__(256, 2)
gemm_qkv(const float* __restrict__ A,
         const float* __restrict__ W0, const float* __restrict__ W1,
         const float* __restrict__ W2)
{
    constexpr int BK = 16, GM = 8, LDK = 136;
    extern __shared__ unsigned sm[];
    unsigned* AsH = sm;
    unsigned* BsH = AsH + BK*LDK;
    unsigned* AsL = BsH + BK*LDK;
    unsigned* BsL = AsL + BK*LDK;

    const float* W = (blockIdx.z == 0) ? W0 : (blockIdx.z == 1) ? W1 : W2;
    float* C = (blockIdx.z == 0) ? g_Q : (blockIdx.z == 1) ? g_K : g_V;

    const int tid  = threadIdx.x;
    const int lane = tid & 31;
    const int wid  = tid >> 5;
    const int wm = wid >> 2, wn = wid & 3;
    const int lr = lane >> 2, lc = lane & 3;
    const int m0 = blockIdx.y * 128;
    const int n0 = blockIdx.x * 128;

    float acc[4][4][4];
    #pragma unroll
    for (int a=0;a<4;a++)
        #pragma unroll
        for (int b=0;b<4;b++)
            #pragma unroll
            for (int c=0;c<4;c++) acc[a][b][c]=0.f;

    for (int kb = 0; kb < 512; kb += BK) {
        #pragma unroll
        for (int l = 0; l < BK/8; l++) {
            int idx = l*256 + tid;
            int row = idx / (BK/4);
            int kq  = idx % (BK/4);
            float4 v = *(const float4*)(A + (size_t)(m0+row)*512 + kb + kq*4);
            float vv[4] = {v.x, v.y, v.z, v.w};
            int sw = row ^ (GM*kq);
            #pragma unroll
            for (int c = 0; c < 4; c++) {
                int k = kq*4 + c;
                unsigned hi = f2tf(vv[c]);
                AsH[k*LDK + sw] = hi;
                AsL[k*LDK + sw] = f2tf(vv[c] - __uint_as_float(hi));
            }
        }
        #pragma unroll
        for (int l = 0; l < BK/8; l++) {
            int idx = l*256 + tid;
            int k  = idx >> 5;
            int cq = idx & 31;
            float4 v = *(const float4*)(W + (size_t)(kb+k)*512 + n0 + cq*4);
            int colb = (cq*4) ^ (GM*(k>>2));
            uint4 h4;
            h4.x = f2tf(v.x); h4.y = f2tf(v.y); h4.z = f2tf(v.z); h4.w = f2tf(v.w);
            *(uint4*)&BsH[k*LDK + colb] = h4;
            uint4 l4;
            l4.x = f2tf(v.x - __uint_as_float(h4.x));
            l4.y = f2tf(v.y - __uint_as_float(h4.y));
            l4.z = f2tf(v.z - __uint_as_float(h4.z));
            l4.w = f2tf(v.w - __uint_as_float(h4.w));
            *(uint4*)&BsL[k*LDK + colb] = l4;
        }
        __syncthreads();
        #pragma unroll
        for (int k8 = 0; k8 < BK/8; k8++) {
            const int kk = k8*8 + lc;
            const int g0 = GM * (kk >> 2);
            const int g1 = GM * ((kk+4) >> 2);
            unsigned af[4][4], bf[4][2];
            #pragma unroll
            for (int mt=0; mt<4; mt++) {
                int r = wm*64 + mt*16 + lr;
                af[mt][0] = AsH[kk*LDK     + (r       ^ g0)];
                af[mt][1] = AsH[kk*LDK     + ((r + 8) ^ g0)];
                af[mt][2] = AsH[(kk+4)*LDK + (r       ^ g1)];
                af[mt][3] = AsH[(kk+4)*LDK + ((r + 8) ^ g1)];
            }
            #pragma unroll
            for (int nt=0; nt<4; nt++) {
                int c = wn*32 + nt*8 + lr;
                bf[nt][0] = BsH[kk*LDK     + (c ^ g0)];
                bf[nt][1] = BsH[(kk+4)*LDK + (c ^ g1)];
            }
            #pragma unroll
            for (int mt=0; mt<4; mt++)
                #pragma unroll
                for (int nt=0; nt<4; nt++)
                    mma8(acc[mt][nt], af[mt], bf[nt]);
            unsigned afl[4][4], bfl[4][2];
            #pragma unroll
            for (int mt=0; mt<4; mt++) {
                int r = wm*64 + mt*16 + lr;
                afl[mt][0] = AsL[kk*LDK     + (r       ^ g0)];
                afl[mt][1] = AsL[kk*LDK     + ((r + 8) ^ g0)];
                afl[mt][2] = AsL[(kk+4)*LDK + (r       ^ g1)];
                afl[mt][3] = AsL[(kk+4)*LDK + ((r + 8) ^ g1)];
            }
            #pragma unroll
            for (int nt=0; nt<4; nt++) {
                int c = wn*32 + nt*8 + lr;
                bfl[nt][0] = BsL[kk*LDK     + (c ^ g0)];
                bfl[nt][1] = BsL[(kk+4)*LDK + (c ^ g1)];
            }
            #pragma unroll
            for (int mt=0; mt<4; mt++)
                #pragma unroll
                for (int nt=0; nt<4; nt++) {
                    mma8(acc[mt][nt], af[mt],  bfl[nt]);
                    mma8(acc[mt][nt], afl[mt], bf[nt]);
                }
        }
        __syncthreads();
    }

    #pragma unroll
    for (int mt=0; mt<4; mt++){
        int r = m0 + wm*64 + mt*16 + lr;
        #pragma unroll
        for (int nt=0; nt<4; nt++){
            int c = n0 + wn*32 + nt*8 + lc*2;
            *(float2*)(C + (size_t)r*512 + c)     = make_float2(acc[mt][nt][0], acc[mt][nt][1]);
            *(float2*)(C + (size_t)(r+8)*512 + c) = make_float2(acc[mt][nt][2], acc[mt][nt][3]);
        }
    }
}

// ---------------------------------------------------------------------------
// softmax + AV (unchanged)
// ---------------------------------------------------------------------------
__global__ void __launch_bounds__(256)
softmax_av(float* __restrict__ hout)
{
    const int it = blockIdx.x;
    const int h  = blockIdx.y;
    const int b  = blockIdx.z;
    const int i0 = it * 64;
    extern __shared__ float smf[];
    float* ws = smf;                 // [64][256]
    float* vs = smf + 64*256;        // [32][68]
    const int tid = threadIdx.x;

    const float* Sp = g_S + ((size_t)(b*8 + h)*256 + i0)*256;
    #pragma unroll
    for (int l = 0; l < 16; l++) {
        int idx = l*256 + tid;
        ((float4*)ws)[idx] = ((const float4*)Sp)[idx];
    }
    __syncthreads();

    const int wid = tid >> 5, lane = tid & 31;
    for (int r = wid*8; r < wid*8 + 8; r++) {
        float* row = ws + r*256;
        float v[8];
        float mx = -1e30f;
        #pragma unroll
        for (int e2=0;e2<8;e2++){ v[e2] = row[lane + e2*32]; mx = fmaxf(mx, v[e2]); }
        #pragma unroll
        for (int o=16;o;o>>=1) mx = fmaxf(mx, __shfl_xor_sync(0xffffffffu, mx, o));
        float s = 0.f;
        #pragma unroll
        for (int e2=0;e2<8;e2++){ v[e2] = __expf(v[e2] - mx); s += v[e2]; }
        #pragma unroll
        for (int o=16;o;o>>=1) s += __shfl_xor_sync(0xffffffffu, s, o);
        float inv = 1.f / s;
        #pragma unroll
        for (int e2=0;e2<8;e2++) row[lane + e2*32] = v[e2]*inv;
    }
    __syncthreads();

    const int tx = tid & 15, ty = tid >> 4;
    float acc[4][4];
    #pragma unroll
    for (int p=0;p<4;p++)
        #pragma unroll
        for (int q=0;q<4;q++) acc[p][q]=0.f;

    const float* Vp = g_V + (size_t)b*256*512 + h*64;
    for (int kbv = 0; kbv < 256; kbv += 32) {
        #pragma unroll
        for (int l=0;l<2;l++){
            int idx = l*256 + tid;
            int kk = idx >> 4, dq = idx & 15;
            float4 vv = *(const float4*)(Vp + (size_t)(kbv+kk)*512 + dq*4);
            *(float4*)(vs + kk*68 + dq*4) = vv;
        }
        __syncthreads();
        #pragma unroll
        for (int k=0;k<32;k++){
            float a0 = ws[(ty*4+0)*256 + kbv + k];
            float a1 = ws[(ty*4+1)*256 + kbv + k];
            float a2 = ws[(ty*4+2)*256 + kbv + k];
            float a3 = ws[(ty*4+3)*256 + kbv + k];
            float4 vv = *(float4*)(vs + k*68 + tx*4);
            acc[0][0] += a0*vv.x; acc[0][1] += a0*vv.y; acc[0][2] += a0*vv.z; acc[0][3] += a0*vv.w;
            acc[1][0] += a1*vv.x; acc[1][1] += a1*vv.y; acc[1][2] += a1*vv.z; acc[1][3] += a1*vv.w;
            acc[2][0] += a2*vv.x; acc[2][1] += a2*vv.y; acc[2][2] += a2*vv.z; acc[2][3] += a2*vv.w;
            acc[3][0] += a3*vv.x; acc[3][1] += a3*vv.y; acc[3][2] += a3*vv.z; acc[3][3] += a3*vv.w;
        }
        __syncthreads();
    }

    float* outp = hout + (size_t)(b*256 + i0)*512 + h*64;
    #pragma unroll
    for (int p=0;p<4;p++){
        int r = ty*4 + p;
        *(float4*)(outp + (size_t)r*512 + tx*4) =
            make_float4(acc[p][0], acc[p][1], acc[p][2], acc[p][3]);
    }
}

extern "C" void kernel_launch(void* const* d_in, const int* in_sizes, int n_in,
                              void* d_out, int out_size)
{
    const float* h  = (const float*)d_in[0];
    const float* e  = (const float*)d_in[1];
    const float* Wq = (const float*)d_in[2];
    const float* Wk = (const float*)d_in[3];
    const float* Wv = (const float*)d_in[4];
    const float* We = (const float*)d_in[5];
    float* outp  = (float*)d_out;
    float* h_out = outp;                               // [B,N,H*D]
    float* e_out = outp + (size_t)BB*NN*CC;            // [B,N,N,H*D]

    cudaFuncSetAttribute(softmax_av, cudaFuncAttributeMaxDynamicSharedMemorySize, 75776);
    cudaFuncSetAttribute(mm_big,     cudaFuncAttributeMaxDynamicSharedMemorySize, 102400);

    const size_t gs = 4*16*136*4;   // 34816
    dim3 qg(4, 8, 3);               // z selects Q/K/V
    gemm_qkv<<<qg, 256, gs>>>(h, Wq, Wk, Wv);

    dim3 mg(2, 2048);               // x = n-tiles (256 each), y = m-tiles (128 rows)
    mm_big<<<mg, 256, 102400>>>(e, We, e_out);

    dim3 ag(4, 8, 4);
    softmax_av<<<ag, 256, 75776>>>(h_out);
}

// round 13
// speedup vs baseline: 1.8422x; 1.8422x over previous
#include <cuda_runtime.h>
#include <cstdint>

#define BB 4
#define NN 256
#define CC 512
#define HH 8
#define DD 64

// Scratch (allocation-free rule: device globals)
__device__ float g_Q[BB*NN*CC];
__device__ float g_K[BB*NN*CC];
__device__ float g_V[BB*NN*CC];
__device__ float g_S[BB*HH*NN*NN];   // [b][h][i][j] clamped score sums
__device__ float g_Wr[CC*CC];        // RNA-tf32-rounded We (f32 bit patterns)

__device__ __forceinline__ unsigned f2tf(float x){
    unsigned r; asm("cvt.rna.tf32.f32 %0, %1;" : "=r"(r) : "f"(x)); return r;
}
__device__ __forceinline__ uint32_t smem_u32(const void* p){
    uint32_t a; asm("{ .reg .u64 t; cvta.to.shared.u64 t, %1; cvt.u32.u64 %0, t; }"
                    : "=r"(a) : "l"(p)); return a;
}

__device__ __forceinline__ void mma8(float* c, const unsigned* a, const unsigned* b){
    asm volatile("mma.sync.aligned.m16n8k8.row.col.f32.tf32.tf32.f32 "
        "{%0,%1,%2,%3}, {%4,%5,%6,%7}, {%8,%9}, {%0,%1,%2,%3};\n"
        : "+f"(c[0]), "+f"(c[1]), "+f"(c[2]), "+f"(c[3])
        : "r"(a[0]), "r"(a[1]), "r"(a[2]), "r"(a[3]), "r"(b[0]), "r"(b[1]));
}

#define CP16(sa, gp) asm volatile("cp.async.cg.shared.global [%0], [%1], 16;" :: "r"(sa), "l"(gp))
#define CP_COMMIT()  asm volatile("cp.async.commit_group;" ::: "memory")
#define CP_WAIT2()   asm volatile("cp.async.wait_group 2;" ::: "memory")

// Pre-round We to RNA tf32 grid (keeps B-side at R3 accuracy; A-side is
// HW-truncated f32->tf32 inside HMMA, the "free tf32" path).
__global__ void wround(const float* __restrict__ W, float* __restrict__ Wr){
    int i = blockIdx.x*256 + threadIdx.x;
    Wr[i] = __uint_as_float(f2tf(W[i]));
}

// ---------------------------------------------------------------------------
// Main GEMM + fused attention epilogue. R3's proven shape (block 128x128,
// 8 warps as 2x4 of 64x32 tiles, 128 regs, 2 CTAs/SM) with the operand
// staging replaced by a 3-stage cp.async pipeline:
//  - no f32->tf32 cvt (HMMA truncates f32 operands in HW; B pre-rounded RNA)
//  - no STS / LDG staging instructions (~60 fewer instrs/thread/ktile;
//    R3 was issue 48.8% / alu 42.7% bound)
//  - 2 tiles always in flight -> gmem latency off the critical path.
// Layouts (bank-verified conflict-free, 16B-aligned for cp.async):
//  A row-major [row][36 words] (fragment-load bank = lane + const),
//  B k-major [k][136 words] (bank = 8lc + lr + 8nt, 32 distinct).
// Pipeline ledger: prologue commits {0,1,2}; each iter wait_group 2 retires
// stage kb%3's group; tail iters commit empty groups to keep the count sane.
// Epilogue identical to R3: val = acc * Q[b,i,c] * K[b,j,c]/8 -> e_out,
// clamped per-(row,head) sums -> g_S.
// ---------------------------------------------------------------------------
__global__ void __launch_bounds__(256, 2)
mm_cp(const float* __restrict__ A, const float* __restrict__ W,
      float* __restrict__ C)
{
    extern __shared__ unsigned sm[];
    const uint32_t sb = smem_u32(sm);
    // stage: A 128*36=4608 w (18432B) + B 32*136=4352 w (17408B) = 8960 w
    const int STG = 8960;

    const int tid  = threadIdx.x;
    const int lane = tid & 31;
    const int wid  = tid >> 5;
    const int wm = wid >> 2, wn = wid & 3;
    const int lr = lane >> 2, lc = lane & 3;
    const size_t m0 = (size_t)blockIdx.y * 128;
    const int n0 = blockIdx.x * 128;

    // per-thread cp.async coordinates (fixed across tiles)
    const int ar = tid >> 3, aq = tid & 7;        // +l*32 rows
    const int bk = tid >> 5, bq = tid & 31;       // +l*8 k-rows

    auto issue_stage = [&](int s, int kb){
        uint32_t ab = sb + (uint32_t)s*STG*4;
        uint32_t bb = ab + 18432;
        #pragma unroll
        for (int l = 0; l < 4; l++){
            int row = ar + l*32;
            CP16(ab + (uint32_t)(row*36 + aq*4)*4,
                 A + (m0 + row)*512 + kb*32 + aq*4);
        }
        #pragma unroll
        for (int l = 0; l < 4; l++){
            int k = bk + l*8;
            CP16(bb + (uint32_t)(k*136 + bq*4)*4,
                 W + (size_t)(kb*32 + k)*512 + n0 + bq*4);
        }
    };

    float acc[4][4][4];
    #pragma unroll
    for (int a=0;a<4;a++)
        #pragma unroll
        for (int b=0;b<4;b++)
            #pragma unroll
            for (int c=0;c<4;c++) acc[a][b][c]=0.f;

    // prologue: 3 stages in flight
    issue_stage(0, 0); CP_COMMIT();
    issue_stage(1, 1); CP_COMMIT();
    issue_stage(2, 2); CP_COMMIT();

    for (int kb = 0; kb < 16; kb++){
        CP_WAIT2();             // oldest group (stage kb%3) complete
        __syncthreads();
        const int cur = kb - (kb/3)*3;
        const unsigned* As = sm + cur*STG;
        const unsigned* Bs = As + 4608;

        #pragma unroll
        for (int k8 = 0; k8 < 4; k8++){
            const int kk = k8*8 + lc;
            unsigned af[4][4], bf[4][2];
            #pragma unroll
            for (int mt=0; mt<4; mt++){
                int r = wm*64 + mt*16 + lr;
                af[mt][0] = As[r*36 + kk];
                af[mt][1] = As[(r+8)*36 + kk];
                af[mt][2] = As[r*36 + kk + 4];
                af[mt][3] = As[(r+8)*36 + kk + 4];
            }
            #pragma unroll
            for (int nt=0; nt<4; nt++){
                int c = wn*32 + nt*8 + lr;
                bf[nt][0] = Bs[kk*136 + c];
                bf[nt][1] = Bs[(kk+4)*136 + c];
            }
            #pragma unroll
            for (int mt=0; mt<4; mt++)
                #pragma unroll
                for (int nt=0; nt<4; nt++)
                    mma8(acc[mt][nt], af[mt], bf[nt]);
        }
        __syncthreads();        // all reads of stage cur done
        if (kb + 3 < 16) issue_stage(cur, kb + 3);
        CP_COMMIT();            // commit every iter (tail keeps wait_group sane)
    }
    __syncthreads();            // before reusing stage smem for rs

    // ---------------- fused epilogue (R3) ----------------
    float* rs = (float*)sm;     // 256 floats: 128 rows x 2 heads
    rs[tid] = 0.f;
    __syncthreads();

    const int bidx = (int)(m0 >> 16);
    const int ii   = (int)((m0 >> 8) & 255);
    const int j0   = (int)(m0 & 255);
    const float* Qrow = g_Q + (size_t)(bidx*256 + ii)*512;
    const float* Kb   = g_K + (size_t)bidx*256*512;
    float qv[4][2];
    #pragma unroll
    for (int nt=0; nt<4; nt++){
        int c = n0 + wn*32 + nt*8 + lc*2;
        qv[nt][0] = Qrow[c]   * 0.125f;
        qv[nt][1] = Qrow[c+1] * 0.125f;
    }
    const int hl = wn >> 1;     // each warp's 32 cols live in one head
    #pragma unroll
    for (int mt=0; mt<4; mt++){
        int rlA = wm*64 + mt*16 + lr;
        int rlB = rlA + 8;
        const float* KrA = Kb + (size_t)(j0 + rlA)*512;
        const float* KrB = Kb + (size_t)(j0 + rlB)*512;
        float pA = 0.f, pB = 0.f;
        #pragma unroll
        for (int nt=0; nt<4; nt++){
            int c = n0 + wn*32 + nt*8 + lc*2;
            float v0 = acc[mt][nt][0] * qv[nt][0] * KrA[c];
            float v1 = acc[mt][nt][1] * qv[nt][1] * KrA[c+1];
            float v2 = acc[mt][nt][2] * qv[nt][0] * KrB[c];
            float v3 = acc[mt][nt][3] * qv[nt][1] * KrB[c+1];
            *(float2*)(C + (m0 + rlA)*512 + c) = make_float2(v0, v1);
            *(float2*)(C + (m0 + rlB)*512 + c) = make_float2(v2, v3);
            pA += v0 + v1;
            pB += v2 + v3;
        }
        pA += __shfl_xor_sync(0xffffffffu, pA, 1);
        pA += __shfl_xor_sync(0xffffffffu, pA, 2);
        pB += __shfl_xor_sync(0xffffffffu, pB, 1);
        pB += __shfl_xor_sync(0xffffffffu, pB, 2);
        if (lc == 0){
            atomicAdd(&rs[rlA*2 + hl], pA);
            atomicAdd(&rs[rlB*2 + hl], pB);
        }
    }
    __syncthreads();
    {
        int rl  = tid >> 1;
        int hl2 = tid & 1;
        int hh  = (n0 >> 6) + hl2;
        float sv = rs[tid];
        sv = fminf(fmaxf(sv, -5.f), 5.f);
        g_S[(((size_t)(bidx*8 + hh))*256 + ii)*256 + j0 + rl] = sv;
    }
}

// ---------------------------------------------------------------------------
// QKV projections: one launch, blockIdx.z selects {Wq,Wk,Wv} -> {g_Q,g_K,g_V}.
// 3x tf32 split, swizzled smem (verified conflict-free). Unchanged (62us).
// ---------------------------------------------------------------------------
__global__ void __launch_bounds__(256, 2)
gemm_qkv(const float* __restrict__ A,
         const float* __restrict__ W0, const float* __restrict__ W1,
         const float* __restrict__ W2)
{
    constexpr int BK = 16, GM = 8, LDK = 136;
    extern __shared__ unsigned sm[];
    unsigned* AsH = sm;
    unsigned* BsH = AsH + BK*LDK;
    unsigned* AsL = BsH + BK*LDK;
    unsigned* BsL = AsL + BK*LDK;

    const float* W = (blockIdx.z == 0) ? W0 : (blockIdx.z == 1) ? W1 : W2;
    float* C = (blockIdx.z == 0) ? g_Q : (blockIdx.z == 1) ? g_K : g_V;

    const int tid  = threadIdx.x;
    const int lane = tid & 31;
    const int wid  = tid >> 5;
    const int wm = wid >> 2, wn = wid & 3;
    const int lr = lane >> 2, lc = lane & 3;
    const int m0 = blockIdx.y * 128;
    const int n0 = blockIdx.x * 128;

    float acc[4][4][4];
    #pragma unroll
    for (int a=0;a<4;a++)
        #pragma unroll
        for (int b=0;b<4;b++)
            #pragma unroll
            for (int c=0;c<4;c++) acc[a][b][c]=0.f;

    for (int kb = 0; kb < 512; kb += BK) {
        #pragma unroll
        for (int l = 0; l < BK/8; l++) {
            int idx = l*256 + tid;
            int row = idx / (BK/4);
            int kq  = idx % (BK/4);
            float4 v = *(const float4*)(A + (size_t)(m0+row)*512 + kb + kq*4);
            float vv[4] = {v.x, v.y, v.z, v.w};
            int sw = row ^ (GM*kq);
            #pragma unroll
            for (int c = 0; c < 4; c++) {
                int k = kq*4 + c;
                unsigned hi = f2tf(vv[c]);
                AsH[k*LDK + sw] = hi;
                AsL[k*LDK + sw] = f2tf(vv[c] - __uint_as_float(hi));
            }
        }
        #pragma unroll
        for (int l = 0; l < BK/8; l++) {
            int idx = l*256 + tid;
            int k  = idx >> 5;
            int cq = idx & 31;
            float4 v = *(const float4*)(W + (size_t)(kb+k)*512 + n0 + cq*4);
            int colb = (cq*4) ^ (GM*(k>>2));
            uint4 h4;
            h4.x = f2tf(v.x); h4.y = f2tf(v.y); h4.z = f2tf(v.z); h4.w = f2tf(v.w);
            *(uint4*)&BsH[k*LDK + colb] = h4;
            uint4 l4;
            l4.x = f2tf(v.x - __uint_as_float(h4.x));
            l4.y = f2tf(v.y - __uint_as_float(h4.y));
            l4.z = f2tf(v.z - __uint_as_float(h4.z));
            l4.w = f2tf(v.w - __uint_as_float(h4.w));
            *(uint4*)&BsL[k*LDK + colb] = l4;
        }
        __syncthreads();
        #pragma unroll
        for (int k8 = 0; k8 < BK/8; k8++) {
            const int kk = k8*8 + lc;
            const int g0 = GM * (kk >> 2);
            const int g1 = GM * ((kk+4) >> 2);
            unsigned af[4][4], bf[4][2];
            #pragma unroll
            for (int mt=0; mt<4; mt++) {
                int r = wm*64 + mt*16 + lr;
                af[mt][0] = AsH[kk*LDK     + (r       ^ g0)];
                af[mt][1] = AsH[kk*LDK     + ((r + 8) ^ g0)];
                af[mt][2] = AsH[(kk+4)*LDK + (r       ^ g1)];
                af[mt][3] = AsH[(kk+4)*LDK + ((r + 8) ^ g1)];
            }
            #pragma unroll
            for (int nt=0; nt<4; nt++) {
                int c = wn*32 + nt*8 + lr;
                bf[nt][0] = BsH[kk*LDK     + (c ^ g0)];
                bf[nt][1] = BsH[(kk+4)*LDK + (c ^ g1)];
            }
            #pragma unroll
            for (int mt=0; mt<4; mt++)
                #pragma unroll
                for (int nt=0; nt<4; nt++)
                    mma8(acc[mt][nt], af[mt], bf[nt]);
            unsigned afl[4][4], bfl[4][2];
            #pragma unroll
            for (int mt=0; mt<4; mt++) {
                int r = wm*64 + mt*16 + lr;
                afl[mt][0] = AsL[kk*LDK     + (r       ^ g0)];
                afl[mt][1] = AsL[kk*LDK     + ((r + 8) ^ g0)];
                afl[mt][2] = AsL[(kk+4)*LDK + (r       ^ g1)];
                afl[mt][3] = AsL[(kk+4)*LDK + ((r + 8) ^ g1)];
            }
            #pragma unroll
            for (int nt=0; nt<4; nt++) {
                int c = wn*32 + nt*8 + lr;
                bfl[nt][0] = BsL[kk*LDK     + (c ^ g0)];
                bfl[nt][1] = BsL[(kk+4)*LDK + (c ^ g1)];
            }
            #pragma unroll
            for (int mt=0; mt<4; mt++)
                #pragma unroll
                for (int nt=0; nt<4; nt++) {
                    mma8(acc[mt][nt], af[mt],  bfl[nt]);
                    mma8(acc[mt][nt], afl[mt], bf[nt]);
                }
        }
        __syncthreads();
    }

    #pragma unroll
    for (int mt=0; mt<4; mt++){
        int r = m0 + wm*64 + mt*16 + lr;
        #pragma unroll
        for (int nt=0; nt<4; nt++){
            int c = n0 + wn*32 + nt*8 + lc*2;
            *(float2*)(C + (size_t)r*512 + c)     = make_float2(acc[mt][nt][0], acc[mt][nt][1]);
            *(float2*)(C + (size_t)(r+8)*512 + c) = make_float2(acc[mt][nt][2], acc[mt][nt][3]);
        }
    }
}

// ---------------------------------------------------------------------------
// softmax + AV (unchanged)
// ---------------------------------------------------------------------------
__global__ void __launch_bounds__(256)
softmax_av(float* __restrict__ hout)
{
    const int it = blockIdx.x;
    const int h  = blockIdx.y;
    const int b  = blockIdx.z;
    const int i0 = it * 64;
    extern __shared__ float smf[];
    float* ws = smf;                 // [64][256]
    float* vs = smf + 64*256;        // [32][68]
    const int tid = threadIdx.x;

    const float* Sp = g_S + ((size_t)(b*8 + h)*256 + i0)*256;
    #pragma unroll
    for (int l = 0; l < 16; l++) {
        int idx = l*256 + tid;
        ((float4*)ws)[idx] = ((const float4*)Sp)[idx];
    }
    __syncthreads();

    const int wid = tid >> 5, lane = tid & 31;
    for (int r = wid*8; r < wid*8 + 8; r++) {
        float* row = ws + r*256;
        float v[8];
        float mx = -1e30f;
        #pragma unroll
        for (int e2=0;e2<8;e2++){ v[e2] = row[lane + e2*32]; mx = fmaxf(mx, v[e2]); }
        #pragma unroll
        for (int o=16;o;o>>=1) mx = fmaxf(mx, __shfl_xor_sync(0xffffffffu, mx, o));
        float s = 0.f;
        #pragma unroll
        for (int e2=0;e2<8;e2++){ v[e2] = __expf(v[e2] - mx); s += v[e2]; }
        #pragma unroll
        for (int o=16;o;o>>=1) s += __shfl_xor_sync(0xffffffffu, s, o);
        float inv = 1.f / s;
        #pragma unroll
        for (int e2=0;e2<8;e2++) row[lane + e2*32] = v[e2]*inv;
    }
    __syncthreads();

    const int tx = tid & 15, ty = tid >> 4;
    float acc[4][4];
    #pragma unroll
    for (int p=0;p<4;p++)
        #pragma unroll
        for (int q=0;q<4;q++) acc[p][q]=0.f;

    const float* Vp = g_V + (size_t)b*256*512 + h*64;
    for (int kbv = 0; kbv < 256; kbv += 32) {
        #pragma unroll
        for (int l=0;l<2;l++){
            int idx = l*256 + tid;
            int kk = idx >> 4, dq = idx & 15;
            float4 vv = *(const float4*)(Vp + (size_t)(kbv+kk)*512 + dq*4);
            *(float4*)(vs + kk*68 + dq*4) = vv;
        }
        __syncthreads();
        #pragma unroll
        for (int k=0;k<32;k++){
            float a0 = ws[(ty*4+0)*256 + kbv + k];
            float a1 = ws[(ty*4+1)*256 + kbv + k];
            float a2 = ws[(ty*4+2)*256 + kbv + k];
            float a3 = ws[(ty*4+3)*256 + kbv + k];
            float4 vv = *(float4*)(vs + k*68 + tx*4);
            acc[0][0] += a0*vv.x; acc[0][1] += a0*vv.y; acc[0][2] += a0*vv.z; acc[0][3] += a0*vv.w;
            acc[1][0] += a1*vv.x; acc[1][1] += a1*vv.y; acc[1][2] += a1*vv.z; acc[1][3] += a1*vv.w;
            acc[2][0] += a2*vv.x; acc[2][1] += a2*vv.y; acc[2][2] += a2*vv.z; acc[2][3] += a2*vv.w;
            acc[3][0] += a3*vv.x; acc[3][1] += a3*vv.y; acc[3][2] += a3*vv.z; acc[3][3] += a3*vv.w;
        }
        __syncthreads();
    }

    float* outp = hout + (size_t)(b*256 + i0)*512 + h*64;
    #pragma unroll
    for (int p=0;p<4;p++){
        int r = ty*4 + p;
        *(float4*)(outp + (size_t)r*512 + tx*4) =
            make_float4(acc[p][0], acc[p][1], acc[p][2], acc[p][3]);
    }
}

extern "C" void kernel_launch(void* const* d_in, const int* in_sizes, int n_in,
                              void* d_out, int out_size)
{
    const float* h  = (const float*)d_in[0];
    const float* e  = (const float*)d_in[1];
    const float* Wq = (const float*)d_in[2];
    const float* Wk = (const float*)d_in[3];
    const float* Wv = (const float*)d_in[4];
    const float* We = (const float*)d_in[5];
    float* outp  = (float*)d_out;
    float* h_out = outp;                               // [B,N,H*D]
    float* e_out = outp + (size_t)BB*NN*CC;            // [B,N,N,H*D]

    float* pWr;
    cudaGetSymbolAddress((void**)&pWr, g_Wr);

    cudaFuncSetAttribute(softmax_av, cudaFuncAttributeMaxDynamicSharedMemorySize, 75776);
    cudaFuncSetAttribute(mm_cp,      cudaFuncAttributeMaxDynamicSharedMemorySize, 107520);

    wround<<<1024, 256>>>(We, pWr);

    const size_t gs = 4*16*136*4;   // 34816
    dim3 qg(4, 8, 3);               // z selects Q/K/V
    gemm_qkv<<<qg, 256, gs>>>(h, Wq, Wk, Wv);

    dim3 mg(4, 2048);               // x = n-tiles (fast axis: L2 reuse of A)
    mm_cp<<<mg, 256, 107520>>>(e, pWr, e_out);

    dim3 ag(4, 8, 4);
    softmax_av<<<ag, 256, 75776>>>(h_out);
}